// round 1
// baseline (speedup 1.0000x reference)
#include <cuda_runtime.h>

#define FULL 0xffffffffu
#define L2E 1.4426950408889634f

struct TreeParams {
    const float* w[9];
    const float* b[9];
    const float* alpha;
    const float* beta;
    const float* gamma;
    const float* root_w;
    const float* root_b;
};

__device__ __forceinline__ float ex2f(float x) {
    float y; asm("ex2.approx.ftz.f32 %0, %1;" : "=f"(y) : "f"(x)); return y;
}
__device__ __forceinline__ float rcpf(float x) {
    float y; asm("rcp.approx.ftz.f32 %0, %1;" : "=f"(y) : "f"(x)); return y;
}

// nck(z) = alpha*0.0878*(z-113.68)/(1+exp(6.39 - z/8.98))
//        + beta *0.129 *(z-69.62)/(1+exp(-4.4 - z/4.25))
//        + gamma*2.23/(0.436 + exp(-0.132*(z-16.74)))
// exp(t) computed as ex2(t*log2e); alpha/beta/gamma folded into cA/dA/cB/dB/cG.
__device__ __forceinline__ float nck_eval(float z, float cA, float dA,
                                          float cB, float dB, float cG) {
    float e1 = ex2f(fmaf(-L2E / 8.98f, z, 6.39f * L2E));
    float e2 = ex2f(fmaf(-L2E / 4.25f, z, -4.4f * L2E));
    float e3 = ex2f(fmaf(-0.132f * L2E, z, 0.132f * 16.74f * L2E));
    float r1 = rcpf(1.0f + e1);
    float r2 = rcpf(1.0f + e2);
    float r3 = rcpf(0.436f + e3);
    float n1 = fmaf(cA, z, dA);
    float n2 = fmaf(cB, z, dB);
    return fmaf(n1, r1, fmaf(n2, r2, cG * r3));
}

// One warp per batch element. 256-leaf binary tree:
//   levels 0-3: lane-packed adjacent-pair reduce; reversal == shfl.xor(31) + slot flip
//   levels 4-8: sub-warp shuffles with clamped indices
__global__ __launch_bounds__(256) void asym_tree_kernel(
    const float* __restrict__ x, TreeParams P, float* __restrict__ out, int B) {
    __shared__ float sw[768];   // weights, level0 pre-reversed
    __shared__ float sb[512];   // biases, level0 pre-reversed, others sliced to live nodes
    __shared__ float sscal[5];  // alpha, beta, gamma, root_w, root_b

    const int tid = threadIdx.x;

    // ---- stage params in shared ----
    // level 0 (reversed): sw[r] = w0[255-r], sb[r] = b0[510-r]
    for (int i = tid; i < 256; i += 256) {
        sw[i] = P.w[0][255 - i];
        sb[i] = P.b[0][510 - i];
    }
    {
        const int WOFF[9] = {0, 256, 512, 640, 704, 736, 752, 760, 764};
        const int BOFF[9] = {0, 256, 384, 448, 480, 496, 504, 508, 510};
#pragma unroll
        for (int l = 1; l < 9; ++l) {
            const int N = 1 << (8 - l);
            for (int i = tid; i < 2 * N; i += 256) sw[WOFF[l] + i] = P.w[l][i];
            for (int i = tid; i < N; i += 256) sb[BOFF[l] + i] = P.b[l][(N - 1) + i];
        }
    }
    if (tid == 0) {
        sscal[0] = P.alpha[0];  sscal[1] = P.beta[0]; sscal[2] = P.gamma[0];
        sscal[3] = P.root_w[0]; sscal[4] = P.root_b[0];
    }
    __syncthreads();

    const float A = sscal[0], Bt = sscal[1], G = sscal[2];
    const float cA = A * 0.0878f, dA = -A * 0.0878f * 113.68f;
    const float cB = Bt * 0.129f, dB = -Bt * 0.129f * 69.62f;
    const float cG = G * 2.23f;

    const int lane = tid & 31;
    const int e = (blockIdx.x * 256 + tid) >> 5;
    if (e >= B) return;

    // ---- level 0: 8 leaves per lane, coalesced float4 loads ----
    const float* xe = x + (size_t)e * 256;
    const float4 xa = reinterpret_cast<const float4*>(xe)[lane * 2];
    const float4 xb = reinterpret_cast<const float4*>(xe)[lane * 2 + 1];
    const float xv[8] = {xa.x, xa.y, xa.z, xa.w, xb.x, xb.y, xb.z, xb.w};

    float u[8];
#pragma unroll
    for (int t = 0; t < 8; ++t) {
        const int r = lane * 8 + t;
        u[t] = nck_eval(fmaf(sw[r], xv[t], sb[r]), cA, dA, cB, dB, cG);
    }

    // ---- level 1: N=128, 4 outputs/lane ----
    float t1[4];
#pragma unroll
    for (int s = 0; s < 4; ++s) {
        const int k = lane * 4 + s;
        const float z = fmaf(sw[256 + 2 * k], u[2 * s],
                       fmaf(sw[256 + 2 * k + 1], u[2 * s + 1], sb[256 + k]));
        t1[s] = nck_eval(z, cA, dA, cB, dB, cG);
    }
#pragma unroll
    for (int s = 0; s < 4; ++s) u[s] = __shfl_xor_sync(FULL, t1[3 - s], 31);

    // ---- level 2: N=64, 2 outputs/lane ----
    float t2[2];
#pragma unroll
    for (int s = 0; s < 2; ++s) {
        const int k = lane * 2 + s;
        const float z = fmaf(sw[512 + 2 * k], u[2 * s],
                       fmaf(sw[512 + 2 * k + 1], u[2 * s + 1], sb[384 + k]));
        t2[s] = nck_eval(z, cA, dA, cB, dB, cG);
    }
    u[0] = __shfl_xor_sync(FULL, t2[1], 31);
    u[1] = __shfl_xor_sync(FULL, t2[0], 31);

    // ---- level 3: N=32, 1 output/lane ----
    {
        const float z = fmaf(sw[640 + 2 * lane], u[0],
                       fmaf(sw[640 + 2 * lane + 1], u[1], sb[448 + lane]));
        u[0] = __shfl_xor_sync(FULL, nck_eval(z, cA, dA, cB, dB, cG), 31);
    }

    // ---- levels 4..8: N = 16, 8, 4, 2, 1 ----
    float cur = u[0];
    const int WO[5] = {704, 736, 752, 760, 764};
    const int BO[5] = {480, 496, 504, 508, 510};
#pragma unroll
    for (int li = 0; li < 5; ++li) {
        const int N = 16 >> li;
        const float a  = __shfl_sync(FULL, cur, (2 * lane) & 31);
        const float bb = __shfl_sync(FULL, cur, (2 * lane + 1) & 31);
        const int k = lane < N ? lane : (N - 1);  // clamp so idle lanes stay in-bounds
        const float z = fmaf(sw[WO[li] + 2 * k], a,
                       fmaf(sw[WO[li] + 2 * k + 1], bb, sb[BO[li] + k]));
        const float t = nck_eval(z, cA, dA, cB, dB, cG);
        cur = __shfl_sync(FULL, t, (N - 1 - lane) & 31);
    }

    // ---- root: sigmoid(v8[0]*root_w + root_b) ----
    if (lane == 0) {
        const float t = fmaf(cur, sscal[3], sscal[4]);
        out[e] = rcpf(1.0f + ex2f(-t * L2E));
    }
}

extern "C" void kernel_launch(void* const* d_in, const int* in_sizes, int n_in,
                              void* d_out, int out_size) {
    const float* x = (const float*)d_in[0];
    TreeParams P;
    // Auto-detect input layout: interleaved (x,w0,b0,w1,b1,...) vs grouped
    // (x,w0..w8,b0..b8). b arrays have 511 elems; w1 has 256.
    if (in_sizes[2] == 511) {
        for (int l = 0; l < 9; ++l) {
            P.w[l] = (const float*)d_in[1 + 2 * l];
            P.b[l] = (const float*)d_in[2 + 2 * l];
        }
    } else {
        for (int l = 0; l < 9; ++l) {
            P.w[l] = (const float*)d_in[1 + l];
            P.b[l] = (const float*)d_in[10 + l];
        }
    }
    P.alpha  = (const float*)d_in[19];
    P.beta   = (const float*)d_in[20];
    P.gamma  = (const float*)d_in[21];
    P.root_w = (const float*)d_in[22];
    P.root_b = (const float*)d_in[23];

    const int B = in_sizes[0] / 256;      // 32768
    const int grid = (B + 7) / 8;         // 8 elements (warps) per 256-thread block
    asym_tree_kernel<<<grid, 256>>>(x, P, (float*)d_out, B);
}

// round 2
// speedup vs baseline: 1.2775x; 1.2775x over previous
#include <cuda_runtime.h>

#define FULL 0xffffffffu
#define L2E 1.4426950408889634f

struct TreeParams {
    const float* w[9];
    const float* b[9];
    const float* alpha;
    const float* beta;
    const float* gamma;
    const float* root_w;
    const float* root_b;
};

__device__ __forceinline__ float ex2f(float x) {
    float y; asm("ex2.approx.ftz.f32 %0, %1;" : "=f"(y) : "f"(x)); return y;
}
__device__ __forceinline__ float rcpf(float x) {
    float y; asm("rcp.approx.ftz.f32 %0, %1;" : "=f"(y) : "f"(x)); return y;
}

// nck(z) = cA*z+dA over (1+e1)  +  cB*z+dB over (1+e2)  +  cG over (0.436+e3)
// computed with a single reciprocal over the common denominator.
// z clamped at -170: for z <= -170 all three terms are < 1e-9, and the clamp
// keeps the denominator product below FLT_MAX (exponent sum 4.2+0.479*170 ~ e^85.6).
__device__ __forceinline__ float nck_eval(float z, float cA, float dA,
                                          float cB, float dB, float cG) {
    z = fmaxf(z, -170.0f);
    const float e1 = ex2f(fmaf(-L2E / 8.98f, z, 6.39f * L2E));
    const float e2 = ex2f(fmaf(-L2E / 4.25f, z, -4.4f * L2E));
    const float e3 = ex2f(fmaf(-0.132f * L2E, z, 0.132f * 16.74f * L2E));
    const float a1 = 1.0f + e1;
    const float a2 = 1.0f + e2;
    const float a3 = 0.436f + e3;
    const float d12 = a1 * a2;
    const float R = rcpf(d12 * a3);
    const float n1 = fmaf(cA, z, dA);
    const float n2 = fmaf(cB, z, dB);
    const float q = fmaf(n1, a2, n2 * a1);
    const float num = fmaf(q, a3, cG * d12);
    return num * R;
}

// One warp per 4 batch elements.
//   levels 0-3: per element, lane-packed adjacent-pair reduce (reversal = shfl.xor 31)
//   levels 4-8: 4 elements packed across lanes; reversal fused into child gather
//               indices (children of output k are at 2N-1-2k, 2N-2-2k in natural order)
__global__ __launch_bounds__(256) void asym_tree_kernel(
    const float* __restrict__ x, TreeParams P, float* __restrict__ out, int B) {
    __shared__ float sw[768];   // weights, level0 pre-reversed
    __shared__ float sb[512];   // biases, level0 pre-reversed, others sliced to live nodes
    __shared__ float sscal[5];

    const int tid = threadIdx.x;

    for (int i = tid; i < 256; i += 256) {
        sw[i] = P.w[0][255 - i];
        sb[i] = P.b[0][510 - i];
    }
    {
        const int WOFF[9] = {0, 256, 512, 640, 704, 736, 752, 760, 764};
        const int BOFF[9] = {0, 256, 384, 448, 480, 496, 504, 508, 510};
#pragma unroll
        for (int l = 1; l < 9; ++l) {
            const int N = 1 << (8 - l);
            for (int i = tid; i < 2 * N; i += 256) sw[WOFF[l] + i] = P.w[l][i];
            for (int i = tid; i < N; i += 256) sb[BOFF[l] + i] = P.b[l][(N - 1) + i];
        }
    }
    if (tid == 0) {
        sscal[0] = P.alpha[0];  sscal[1] = P.beta[0]; sscal[2] = P.gamma[0];
        sscal[3] = P.root_w[0]; sscal[4] = P.root_b[0];
    }
    __syncthreads();

    const float A = sscal[0], Bt = sscal[1], G = sscal[2];
    const float cA = A * 0.0878f, dA = -A * 0.0878f * 113.68f;
    const float cB = Bt * 0.129f, dB = -Bt * 0.129f * 69.62f;
    const float cG = G * 2.23f;

    const int lane = tid & 31;
    const int warp = (blockIdx.x * 256 + tid) >> 5;
    const int e0 = warp * 4;
    if (e0 >= B) return;

    // ---- per-element levels 0-3 -> c[e] = v3 (natural order, one value/lane) ----
    float c[4];
#pragma unroll
    for (int ei = 0; ei < 4; ++ei) {
        const int e = e0 + ei;
        const float* xe = x + (size_t)(e < B ? e : B - 1) * 256;
        const float4 xa = reinterpret_cast<const float4*>(xe)[lane * 2];
        const float4 xb = reinterpret_cast<const float4*>(xe)[lane * 2 + 1];
        const float xv[8] = {xa.x, xa.y, xa.z, xa.w, xb.x, xb.y, xb.z, xb.w};

        float u[8];
#pragma unroll
        for (int t = 0; t < 8; ++t) {
            const int r = lane * 8 + t;
            u[t] = nck_eval(fmaf(sw[r], xv[t], sb[r]), cA, dA, cB, dB, cG);
        }

        // level 1: N=128, 4 outputs/lane
        float t1[4];
#pragma unroll
        for (int s = 0; s < 4; ++s) {
            const int k = lane * 4 + s;
            const float z = fmaf(sw[256 + 2 * k], u[2 * s],
                           fmaf(sw[256 + 2 * k + 1], u[2 * s + 1], sb[256 + k]));
            t1[s] = nck_eval(z, cA, dA, cB, dB, cG);
        }
#pragma unroll
        for (int s = 0; s < 4; ++s) u[s] = __shfl_xor_sync(FULL, t1[3 - s], 31);

        // level 2: N=64, 2 outputs/lane
        float t2[2];
#pragma unroll
        for (int s = 0; s < 2; ++s) {
            const int k = lane * 2 + s;
            const float z = fmaf(sw[512 + 2 * k], u[2 * s],
                           fmaf(sw[512 + 2 * k + 1], u[2 * s + 1], sb[384 + k]));
            t2[s] = nck_eval(z, cA, dA, cB, dB, cG);
        }
        u[0] = __shfl_xor_sync(FULL, t2[1], 31);
        u[1] = __shfl_xor_sync(FULL, t2[0], 31);

        // level 3: N=32, 1 output/lane -> NATURAL order (no trailing reversal)
        const float z3 = fmaf(sw[640 + 2 * lane], u[0],
                        fmaf(sw[640 + 2 * lane + 1], u[1], sb[448 + lane]));
        c[ei] = nck_eval(z3, cA, dA, cB, dB, cG);
    }

    // ---- level 4: N=16, 2 elements per warp-nck (2 packed calls) ----
    const bool hi = lane >= 16;
    const int k4 = lane & 15;
    const int i4a = 31 - 2 * k4;
    const int i4b = 30 - 2 * k4;
    const float w4a = sw[704 + 2 * k4], w4b = sw[704 + 2 * k4 + 1];
    const float bb4 = sb[480 + k4];

    float v4p0, v4p1;
    {
        const float a0 = __shfl_sync(FULL, c[0], i4a);
        const float a1 = __shfl_sync(FULL, c[1], i4a);
        const float b0 = __shfl_sync(FULL, c[0], i4b);
        const float b1 = __shfl_sync(FULL, c[1], i4b);
        const float pa = hi ? a1 : a0;
        const float pb = hi ? b1 : b0;
        v4p0 = nck_eval(fmaf(w4a, pa, fmaf(w4b, pb, bb4)), cA, dA, cB, dB, cG);
    }
    {
        const float a0 = __shfl_sync(FULL, c[2], i4a);
        const float a1 = __shfl_sync(FULL, c[3], i4a);
        const float b0 = __shfl_sync(FULL, c[2], i4b);
        const float b1 = __shfl_sync(FULL, c[3], i4b);
        const float pa = hi ? a1 : a0;
        const float pb = hi ? b1 : b0;
        v4p1 = nck_eval(fmaf(w4a, pa, fmaf(w4b, pb, bb4)), cA, dA, cB, dB, cG);
    }
    // v4p0: lanes 0-15 = e0 (k natural), 16-31 = e1; v4p1: e2, e3.

    // ---- level 5: N=8, all 4 elements in one warp-nck ----
    float v5;
    {
        const int k5 = lane & 7;
        const int half = (lane >> 3) & 1;            // element within source reg
        const int s5a = half * 16 + (15 - 2 * k5);
        const int s5b = s5a - 1;
        const float w5a = sw[736 + 2 * k5], w5b = sw[736 + 2 * k5 + 1];
        const float bb5 = sb[496 + k5];
        const float A0 = __shfl_sync(FULL, v4p0, s5a);
        const float A1 = __shfl_sync(FULL, v4p1, s5a);
        const float B0 = __shfl_sync(FULL, v4p0, s5b);
        const float B1 = __shfl_sync(FULL, v4p1, s5b);
        const float pa = hi ? A1 : A0;
        const float pb = hi ? B1 : B0;
        v5 = nck_eval(fmaf(w5a, pa, fmaf(w5b, pb, bb5)), cA, dA, cB, dB, cG);
    }
    // v5: lane = 8*e + k  (e = 0..3, k = 0..7, natural)

    // ---- level 6: N=4, elements at lanes 0-15 (lane = 4e + k) ----
    float v6;
    {
        const int k6 = lane & 3;
        const int e6 = lane >> 2;
        const int s6 = (8 * e6 + 7 - 2 * k6) & 31;
        const float w6a = sw[752 + 2 * k6], w6b = sw[752 + 2 * k6 + 1];
        const float bb6 = sb[504 + k6];
        const float pa = __shfl_sync(FULL, v5, s6);
        const float pb = __shfl_sync(FULL, v5, (s6 - 1) & 31);
        v6 = nck_eval(fmaf(w6a, pa, fmaf(w6b, pb, bb6)), cA, dA, cB, dB, cG);
    }
    // v6: lane = 4e + k (lanes 0-15 valid)

    // ---- level 7: N=2, lane = 2e + k (lanes 0-7 valid) ----
    float v7;
    {
        const int k7 = lane & 1;
        const int e7 = (lane >> 1) & 7;
        const int s7 = (4 * e7 + 3 - 2 * k7) & 31;
        const float w7a = sw[760 + 2 * k7], w7b = sw[760 + 2 * k7 + 1];
        const float bb7 = sb[508 + k7];
        const float pa = __shfl_sync(FULL, v6, s7);
        const float pb = __shfl_sync(FULL, v6, (s7 - 1) & 31);
        v7 = nck_eval(fmaf(w7a, pa, fmaf(w7b, pb, bb7)), cA, dA, cB, dB, cG);
    }

    // ---- level 8: N=1, lane = e (lanes 0-3 valid) ----
    {
        const int e8 = lane & 3;
        const float w8a = sw[764], w8b = sw[765];
        const float bb8 = sb[510];
        const float pa = __shfl_sync(FULL, v7, (2 * e8 + 1) & 31);  // u[0] = v7[1]
        const float pb = __shfl_sync(FULL, v7, (2 * e8) & 31);      // u[1] = v7[0]
        const float v8 = nck_eval(fmaf(w8a, pa, fmaf(w8b, pb, bb8)),
                                  cA, dA, cB, dB, cG);
        if (lane < 4 && e0 + lane < B) {
            const float t = fmaf(v8, sscal[3], sscal[4]);
            out[e0 + lane] = rcpf(1.0f + ex2f(-t * L2E));
        }
    }
}

extern "C" void kernel_launch(void* const* d_in, const int* in_sizes, int n_in,
                              void* d_out, int out_size) {
    const float* x = (const float*)d_in[0];
    TreeParams P;
    if (in_sizes[2] == 511) {
        for (int l = 0; l < 9; ++l) {
            P.w[l] = (const float*)d_in[1 + 2 * l];
            P.b[l] = (const float*)d_in[2 + 2 * l];
        }
    } else {
        for (int l = 0; l < 9; ++l) {
            P.w[l] = (const float*)d_in[1 + l];
            P.b[l] = (const float*)d_in[10 + l];
        }
    }
    P.alpha  = (const float*)d_in[19];
    P.beta   = (const float*)d_in[20];
    P.gamma  = (const float*)d_in[21];
    P.root_w = (const float*)d_in[22];
    P.root_b = (const float*)d_in[23];

    const int B = in_sizes[0] / 256;              // 32768
    const int warps = (B + 3) / 4;                // 4 elements per warp
    const int grid = (warps + 7) / 8;             // 8 warps per 256-thread block
    asym_tree_kernel<<<grid, 256>>>(x, P, (float*)d_out, B);
}